// round 4
// baseline (speedup 1.0000x reference)
#include <cuda_runtime.h>
#include <cstdint>

#define Nn     100000
#define Ee     3200000
#define FEATS  256
#define CLS    16
#define HID    64
#define DEPTH  20
#define A1W_STRIDE (257*64)

// ---------------- scratch (static device globals; no allocation) ----------------
__device__ int   g_is64;
__device__ int   g_deg[Nn];
__device__ int   g_rowptr[Nn + 1];
__device__ int   g_cursor[Nn];
__device__ int   g_col[Ee];          // src indices sorted by dst (CSR by dst)
__device__ float g_dis[Nn];
__device__ float g_h0[Nn * CLS];     // MLP output (diffusion-1 anchor)
__device__ float g_hA[Nn * CLS];     // diffusion-1 h output
__device__ float g_out0[Nn * CLS];   // head output (diffusion-2 anchor)
__device__ float g_gA[Nn * CLS];     // ping-pong g = dis*h
__device__ float g_gB[Nn * CLS];

// ---------------- helpers ----------------
__device__ __forceinline__ float tf32r(float x) {
    uint32_t y;
    asm("cvt.rna.tf32.f32 %0, %1;" : "=r"(y) : "f"(x));
    return __uint_as_float(y);
}

__device__ __forceinline__ int edge_at(const void* edges, long long idx) {
    if (g_is64) return (int)((const long long*)edges)[idx];
    return ((const int*)edges)[idx];
}

// ---------------- setup kernels ----------------
// Detect int64 vs int32 edge dump: interpret first 4096 int32 words as 2048
// (lo,hi) pairs; node ids < 2^31 so int64 layout => all hi words zero.
__global__ void detect_kernel(const int* __restrict__ e32) {
    int nz = 0;
    for (int i = threadIdx.x; i < 2048; i += 32) nz += (e32[2 * i + 1] != 0);
    for (int o = 16; o; o >>= 1) nz += __shfl_down_sync(0xffffffffu, nz, o);
    if (threadIdx.x == 0) g_is64 = (nz == 0) ? 1 : 0;
}

__global__ void zero_deg_kernel() {
    int n = blockIdx.x * blockDim.x + threadIdx.x;
    if (n < Nn) g_deg[n] = 0;
}

__global__ void deg_kernel(const void* __restrict__ edges) {
    int e = blockIdx.x * blockDim.x + threadIdx.x;
    if (e < Ee) {
        int d = edge_at(edges, (long long)Ee + e);
        atomicAdd(&g_deg[d], 1);
    }
}

__global__ void dis_kernel() {
    int n = blockIdx.x * blockDim.x + threadIdx.x;
    if (n < Nn) {
        int d = g_deg[n];
        g_dis[n] = (d > 0) ? rsqrtf((float)d) : 0.0f;
    }
}

// single-block exclusive scan of g_deg -> g_rowptr (+ g_cursor copy)
__global__ void scan_kernel() {
    __shared__ int buf[1024];
    const int CH = (Nn + 1023) / 1024;   // 98
    int t = threadIdx.x;
    int start = t * CH;
    int end = min(start + CH, Nn);
    int s = 0;
    if (start < Nn) {
        for (int i = start; i < end; i++) s += g_deg[i];
    }
    int mysum = (start < Nn) ? s : 0;
    buf[t] = mysum;
    __syncthreads();
    // inclusive Hillis-Steele
    for (int off = 1; off < 1024; off <<= 1) {
        int v = (t >= off) ? buf[t - off] : 0;
        __syncthreads();
        buf[t] += v;
        __syncthreads();
    }
    int run = buf[t] - mysum;     // exclusive prefix at chunk start
    if (start < Nn) {
        for (int i = start; i < end; i++) {
            g_rowptr[i] = run;
            g_cursor[i] = run;
            run += g_deg[i];
        }
        if (end == Nn) g_rowptr[Nn] = run;
    }
}

__global__ void fill_kernel(const void* __restrict__ edges) {
    int e = blockIdx.x * blockDim.x + threadIdx.x;
    if (e < Ee) {
        int s = edge_at(edges, e);
        int d = edge_at(edges, (long long)Ee + e);
        int p = atomicAdd(&g_cursor[d], 1);
        g_col[p] = s;
    }
}

// ---------------- MLP: h0 = relu(x@W1+b1)@W2 + b2 ; g = dis*h0 ----------------
#define MLP_NB 64
__global__ __launch_bounds__(256) void mlp_kernel(
    const float* __restrict__ x, const float* __restrict__ W1,
    const float* __restrict__ b1, const float* __restrict__ W2,
    const float* __restrict__ b2) {
    __shared__ float xs[MLP_NB][65];   // also reused as hidden
    __shared__ float w1s[64][64];
    __shared__ float w2s[64][16];
    int tid = threadIdx.x;
    int n0 = blockIdx.x * MLP_NB;
    int nq = tid >> 4;    // 0..15 -> node group *4
    int jq = tid & 15;    // 0..15 -> hidden group *4

    for (int i = tid; i < 64 * 16; i += 256) w2s[i >> 4][i & 15] = W2[i];

    float acc[4][4];
#pragma unroll
    for (int i = 0; i < 4; i++)
#pragma unroll
        for (int j = 0; j < 4; j++) acc[i][j] = 0.0f;

    for (int kc = 0; kc < FEATS; kc += 64) {
        for (int i = tid; i < 64 * 64; i += 256) {
            int n = i >> 6, k = i & 63;
            int gn = n0 + n;
            xs[n][k] = (gn < Nn) ? x[(size_t)gn * FEATS + kc + k] : 0.0f;
        }
        for (int i = tid; i < 64 * 64; i += 256) {
            int k = i >> 6, j = i & 63;
            w1s[k][j] = W1[(size_t)(kc + k) * HID + j];
        }
        __syncthreads();
#pragma unroll 8
        for (int k = 0; k < 64; k++) {
            float xv0 = xs[nq * 4 + 0][k];
            float xv1 = xs[nq * 4 + 1][k];
            float xv2 = xs[nq * 4 + 2][k];
            float xv3 = xs[nq * 4 + 3][k];
            float4 w = *reinterpret_cast<const float4*>(&w1s[k][jq * 4]);
            acc[0][0] += xv0 * w.x; acc[0][1] += xv0 * w.y; acc[0][2] += xv0 * w.z; acc[0][3] += xv0 * w.w;
            acc[1][0] += xv1 * w.x; acc[1][1] += xv1 * w.y; acc[1][2] += xv1 * w.z; acc[1][3] += xv1 * w.w;
            acc[2][0] += xv2 * w.x; acc[2][1] += xv2 * w.y; acc[2][2] += xv2 * w.z; acc[2][3] += xv2 * w.w;
            acc[3][0] += xv3 * w.x; acc[3][1] += xv3 * w.y; acc[3][2] += xv3 * w.z; acc[3][3] += xv3 * w.w;
        }
        __syncthreads();
    }
    // relu + bias, store hidden into xs
#pragma unroll
    for (int j = 0; j < 4; j++) {
        float bb = b1[jq * 4 + j];
#pragma unroll
        for (int i = 0; i < 4; i++)
            xs[nq * 4 + i][jq * 4 + j] = fmaxf(acc[i][j] + bb, 0.0f);
    }
    __syncthreads();
    // second layer: 64 nodes x 16 classes
#pragma unroll
    for (int r = 0; r < 4; r++) {
        int idx = tid * 4 + r;
        int n = idx >> 4, c = idx & 15;
        float s = b2[c];
#pragma unroll 8
        for (int k = 0; k < 64; k++) s += xs[n][k] * w2s[k][c];
        int gn = n0 + n;
        if (gn < Nn) {
            g_h0[gn * CLS + c] = s;
            g_gA[gn * CLS + c] = g_dis[gn] * s;
        }
    }
}

// ---------------- diffusion step ----------------
// h_{t+1}[d] = 0.9 * dis[d] * sum_{e in row d} g[src_e] + 0.1 * h0[d];  g = dis*h
__global__ __launch_bounds__(256) void diffuse_kernel(int gsel, int d2, float* __restrict__ h_out_ext) {
    const float* __restrict__ g_in  = gsel ? g_gB : g_gA;
    float* __restrict__ g_out       = gsel ? g_gA : g_gB;
    const float* __restrict__ h0    = d2 ? g_out0 : g_h0;
    float* __restrict__ h_out       = h_out_ext ? h_out_ext : g_hA;

    int t = blockIdx.x * blockDim.x + threadIdx.x;
    int node = t >> 4;
    if (node >= Nn) return;
    int c = t & 15;
    int r0 = g_rowptr[node];
    int r1 = g_rowptr[node + 1];
    float s0 = 0.f, s1 = 0.f, s2 = 0.f, s3 = 0.f;
    int e = r0;
    for (; e + 4 <= r1; e += 4) {
        int i0 = g_col[e], i1 = g_col[e + 1], i2 = g_col[e + 2], i3 = g_col[e + 3];
        s0 += g_in[i0 * CLS + c];
        s1 += g_in[i1 * CLS + c];
        s2 += g_in[i2 * CLS + c];
        s3 += g_in[i3 * CLS + c];
    }
    for (; e < r1; e++) s0 += g_in[g_col[e] * CLS + c];
    float S = (s0 + s1) + (s2 + s3);
    float d = g_dis[node];
    float h = 0.9f * d * S + 0.1f * h0[t];
    h_out[t] = h;
    g_out[t] = d * h;
}

// ---------------- fused head: tf32 MMA GEMM + per-class epilogue ----------------
// out[n,c] = sum_h relu( (x @ A1w[c,1:,:])[n,h] + hA[n,c]*A1w[c,0,h] + A1b[c,h] ) * A2w[c,h] + A2b[c]
// grid: (ceil(N/64), 4). Each block: 64 nodes x 256 output cols (= 4 classes x 64 hidden).
__global__ __launch_bounds__(256, 2) void head_kernel(
    const float* __restrict__ x, const float* __restrict__ A1w,
    const float* __restrict__ A1b, const float* __restrict__ A2w,
    const float* __restrict__ A2b) {
    __shared__ float As[64 * 36];      // [row][k], stride 36 (conflict-free frags)
    __shared__ float Bs[32 * 264];     // [k][j],  stride 264
    __shared__ float a1w0s[4 * 64];
    __shared__ float a1bs[4 * 64];
    __shared__ float a2ws[4 * 64];
    __shared__ float outsum[64 * 4];

    int tid = threadIdx.x;
    int warp = tid >> 5, lane = tid & 31;
    int g = lane >> 2, q = lane & 3;
    int warp_m = warp >> 1;   // 0..3 -> 16-row tile
    int warp_n = warp & 1;    // 0..1 -> 128-col tile
    int n0 = blockIdx.x * 64;
    int c0 = blockIdx.y * 4;  // first class of this block

    for (int i = tid; i < 256; i += 256) {
        int cl = i >> 6, h = i & 63;
        a1w0s[i] = A1w[(size_t)(c0 + cl) * A1W_STRIDE + h];          // A1w[c,0,h]
        a1bs[i]  = A1b[(c0 + cl) * HID + h];
        a2ws[i]  = A2w[(c0 + cl) * HID + h];
    }

    float acc[16][4];
#pragma unroll
    for (int i = 0; i < 16; i++)
#pragma unroll
        for (int j = 0; j < 4; j++) acc[i][j] = 0.0f;

    for (int kc = 0; kc < FEATS; kc += 32) {
        for (int i = tid; i < 64 * 32; i += 256) {
            int r = i >> 5, k = i & 31;
            int gn = n0 + r;
            float v = (gn < Nn) ? x[(size_t)gn * FEATS + kc + k] : 0.0f;
            As[r * 36 + k] = tf32r(v);
        }
        for (int i = tid; i < 32 * 256; i += 256) {
            int k = i >> 8, j = i & 255;
            int cl = j >> 6, h = j & 63;
            float v = A1w[(size_t)(c0 + cl) * A1W_STRIDE + (size_t)(1 + kc + k) * HID + h];
            Bs[k * 264 + j] = tf32r(v);
        }
        __syncthreads();
#pragma unroll
        for (int kk = 0; kk < 4; kk++) {
            int kb = kk * 8;
            int ar = warp_m * 16;
            uint32_t a0 = __float_as_uint(As[(ar + g) * 36 + kb + q]);
            uint32_t a1 = __float_as_uint(As[(ar + g + 8) * 36 + kb + q]);
            uint32_t a2 = __float_as_uint(As[(ar + g) * 36 + kb + q + 4]);
            uint32_t a3 = __float_as_uint(As[(ar + g + 8) * 36 + kb + q + 4]);
#pragma unroll
            for (int nt = 0; nt < 16; nt++) {
                int cb = warp_n * 128 + nt * 8;
                uint32_t b0 = __float_as_uint(Bs[(kb + q) * 264 + cb + g]);
                uint32_t b1 = __float_as_uint(Bs[(kb + q + 4) * 264 + cb + g]);
                asm volatile(
                    "mma.sync.aligned.m16n8k8.row.col.f32.tf32.tf32.f32 "
                    "{%0,%1,%2,%3}, {%4,%5,%6,%7}, {%8,%9}, {%0,%1,%2,%3};"
                    : "+f"(acc[nt][0]), "+f"(acc[nt][1]), "+f"(acc[nt][2]), "+f"(acc[nt][3])
                    : "r"(a0), "r"(a1), "r"(a2), "r"(a3), "r"(b0), "r"(b1));
            }
        }
        __syncthreads();
    }

    // epilogue: z = relu(acc + h*A1w0 + A1b); reduce z*A2w over hidden dim
    int nlA = warp_m * 16 + g;         // local rows this thread owns
    int nlB = nlA + 8;
    float hv[2][2];
#pragma unroll
    for (int rr = 0; rr < 2; rr++) {
#pragma unroll
        for (int ch = 0; ch < 2; ch++) {
            int node = n0 + (rr ? nlB : nlA);
            int cgl = c0 + warp_n * 2 + ch;
            hv[rr][ch] = (node < Nn) ? g_hA[node * CLS + cgl] : 0.0f;
        }
    }
    float p[2][2] = {{0.f, 0.f}, {0.f, 0.f}};
#pragma unroll
    for (int nt = 0; nt < 16; nt++) {
        int clh = nt >> 3;                       // class-half within warp
        int cidx = warp_n * 2 + clh;             // local class 0..3
        int hbase = (nt & 7) * 8 + 2 * q;        // hidden index base
#pragma unroll
        for (int cc = 0; cc < 2; cc++) {
            int h = hbase + cc;
            int sidx = cidx * 64 + h;
            float w0 = a1w0s[sidx], bb = a1bs[sidx], w2 = a2ws[sidx];
            float z0 = fmaxf(acc[nt][cc] + hv[0][clh] * w0 + bb, 0.0f);
            float z1 = fmaxf(acc[nt][2 + cc] + hv[1][clh] * w0 + bb, 0.0f);
            p[0][clh] += z0 * w2;
            p[1][clh] += z1 * w2;
        }
    }
#pragma unroll
    for (int rr = 0; rr < 2; rr++) {
#pragma unroll
        for (int ch = 0; ch < 2; ch++) {
            float v = p[rr][ch];
            v += __shfl_down_sync(0xffffffffu, v, 1, 4);
            v += __shfl_down_sync(0xffffffffu, v, 2, 4);
            if (q == 0) outsum[(warp_m * 16 + g + rr * 8) * 4 + (warp_n * 2 + ch)] = v;
        }
    }
    __syncthreads();
    {
        int nl = tid >> 2, cl = tid & 3;
        int node = n0 + nl;
        int cgl = c0 + cl;
        if (node < Nn) {
            float v = outsum[nl * 4 + cl] + A2b[cgl];
            g_out0[node * CLS + cgl] = v;
            g_gA[node * CLS + cgl] = g_dis[node] * v;   // init g for diffusion 2
        }
    }
}

// ---------------- launch ----------------
extern "C" void kernel_launch(void* const* d_in, const int* in_sizes, int n_in,
                              void* d_out, int out_size) {
    const float* x     = (const float*)d_in[0];
    const void*  edges = d_in[1];
    const float* W1    = (const float*)d_in[2];
    const float* b1    = (const float*)d_in[3];
    const float* W2    = (const float*)d_in[4];
    const float* b2    = (const float*)d_in[5];
    const float* A1w   = (const float*)d_in[6];
    const float* A1b   = (const float*)d_in[7];
    const float* A2w   = (const float*)d_in[8];
    const float* A2b   = (const float*)d_in[9];

    detect_kernel<<<1, 32>>>((const int*)edges);
    zero_deg_kernel<<<(Nn + 255) / 256, 256>>>();
    deg_kernel<<<(Ee + 255) / 256, 256>>>(edges);
    dis_kernel<<<(Nn + 255) / 256, 256>>>();
    scan_kernel<<<1, 1024>>>();
    fill_kernel<<<(Ee + 255) / 256, 256>>>(edges);

    mlp_kernel<<<(Nn + MLP_NB - 1) / MLP_NB, 256>>>(x, W1, b1, W2, b2);

    for (int i = 0; i < DEPTH; i++)
        diffuse_kernel<<<(Nn * CLS + 255) / 256, 256>>>(i & 1, 0, nullptr);

    head_kernel<<<dim3((Nn + 63) / 64, 4), 256>>>(x, A1w, A1b, A2w, A2b);

    for (int i = 0; i < DEPTH; i++)
        diffuse_kernel<<<(Nn * CLS + 255) / 256, 256>>>(i & 1, 1,
            (i == DEPTH - 1) ? (float*)d_out : nullptr);
}

// round 6
// speedup vs baseline: 1.0304x; 1.0304x over previous
#include <cuda_runtime.h>
#include <cstdint>

#define Nn     100000
#define Ee     3200000
#define FEATS  256
#define CLS    16
#define HID    64
#define DEPTH  20
#define A1W_STRIDE (257*64)

// ---------------- scratch (static device globals; no allocation) ----------------
__device__ int   g_is64;
__device__ int   g_deg[Nn];
__device__ int   g_rowptr[Nn + 1];
__device__ int   g_cursor[Nn];
__device__ int   g_col[Ee];          // src indices sorted by dst (CSR by dst)
__device__ float g_dis[Nn];
__device__ float g_dis2[Nn];
__device__ float g_h0[Nn * CLS];     // MLP output (diffusion-1 anchor)
__device__ float g_hA[Nn * CLS];     // diffusion-1 h output
__device__ float g_out0[Nn * CLS];   // head output (diffusion-2 anchor)
__device__ float g_dh0[Nn * CLS];    // dis * h0 (anchor premultiplied)
__device__ float g_gA[Nn * CLS];     // ping-pong g = dis*h
__device__ float g_gB[Nn * CLS];

// ---------------- helpers ----------------
__device__ __forceinline__ float tf32r(float x) {
    uint32_t y;
    asm("cvt.rna.tf32.f32 %0, %1;" : "=r"(y) : "f"(x));
    return __uint_as_float(y);
}

__device__ __forceinline__ int edge_at(const void* edges, long long idx) {
    if (g_is64) return (int)((const long long*)edges)[idx];
    return ((const int*)edges)[idx];
}

// ---------------- setup kernels ----------------
// zero degrees + detect int64 vs int32 edge dump (hi words of int64 pairs == 0)
__global__ void init_kernel(const int* __restrict__ e32) {
    int n = blockIdx.x * blockDim.x + threadIdx.x;
    if (n < Nn) g_deg[n] = 0;
    if (blockIdx.x == 0 && threadIdx.x < 32) {
        int nz = 0;
        for (int i = threadIdx.x; i < 2048; i += 32) nz += (e32[2 * i + 1] != 0);
        for (int o = 16; o; o >>= 1) nz += __shfl_down_sync(0xffffffffu, nz, o);
        if (threadIdx.x == 0) g_is64 = (nz == 0) ? 1 : 0;
    }
}

__global__ void deg_kernel(const void* __restrict__ edges) {
    int e = blockIdx.x * blockDim.x + threadIdx.x;
    if (e < Ee) {
        int d = edge_at(edges, (long long)Ee + e);
        atomicAdd(&g_deg[d], 1);
    }
}

// single-block exclusive scan of g_deg -> g_rowptr (+cursor) + dis/dis2
__global__ void scan_kernel() {
    __shared__ int buf[1024];
    const int CH = (Nn + 1023) / 1024;   // 98
    int t = threadIdx.x;
    int start = t * CH;
    int end = min(start + CH, Nn);
    int s = 0;
    if (start < Nn) {
        for (int i = start; i < end; i++) s += g_deg[i];
    }
    int mysum = (start < Nn) ? s : 0;
    buf[t] = mysum;
    __syncthreads();
    for (int off = 1; off < 1024; off <<= 1) {
        int v = (t >= off) ? buf[t - off] : 0;
        __syncthreads();
        buf[t] += v;
        __syncthreads();
    }
    int run = buf[t] - mysum;
    if (start < Nn) {
        for (int i = start; i < end; i++) {
            int d = g_deg[i];
            g_rowptr[i] = run;
            g_cursor[i] = run;
            float dv = (d > 0) ? rsqrtf((float)d) : 0.0f;
            g_dis[i] = dv;
            g_dis2[i] = dv * dv;
            run += d;
        }
        if (end == Nn) g_rowptr[Nn] = run;
    }
}

__global__ void fill_kernel(const void* __restrict__ edges) {
    int e = blockIdx.x * blockDim.x + threadIdx.x;
    if (e < Ee) {
        int s = edge_at(edges, e);
        int d = edge_at(edges, (long long)Ee + e);
        int p = atomicAdd(&g_cursor[d], 1);
        g_col[p] = s;
    }
}

// ---------------- MLP: h0 = relu(x@W1+b1)@W2 + b2 ; g = dis*h0 ----------------
#define MLP_NB 64
__global__ __launch_bounds__(256) void mlp_kernel(
    const float* __restrict__ x, const float* __restrict__ W1,
    const float* __restrict__ b1, const float* __restrict__ W2,
    const float* __restrict__ b2) {
    __shared__ float xs[MLP_NB][65];
    __shared__ float w1s[64][64];
    __shared__ float w2s[64][16];
    int tid = threadIdx.x;
    int n0 = blockIdx.x * MLP_NB;
    int nq = tid >> 4;
    int jq = tid & 15;

    for (int i = tid; i < 64 * 16; i += 256) w2s[i >> 4][i & 15] = W2[i];

    float acc[4][4];
#pragma unroll
    for (int i = 0; i < 4; i++)
#pragma unroll
        for (int j = 0; j < 4; j++) acc[i][j] = 0.0f;

    for (int kc = 0; kc < FEATS; kc += 64) {
        for (int i = tid; i < 64 * 64; i += 256) {
            int n = i >> 6, k = i & 63;
            int gn = n0 + n;
            xs[n][k] = (gn < Nn) ? x[(size_t)gn * FEATS + kc + k] : 0.0f;
        }
        for (int i = tid; i < 64 * 64; i += 256) {
            int k = i >> 6, j = i & 63;
            w1s[k][j] = W1[(size_t)(kc + k) * HID + j];
        }
        __syncthreads();
#pragma unroll 8
        for (int k = 0; k < 64; k++) {
            float xv0 = xs[nq * 4 + 0][k];
            float xv1 = xs[nq * 4 + 1][k];
            float xv2 = xs[nq * 4 + 2][k];
            float xv3 = xs[nq * 4 + 3][k];
            float4 w = *reinterpret_cast<const float4*>(&w1s[k][jq * 4]);
            acc[0][0] += xv0 * w.x; acc[0][1] += xv0 * w.y; acc[0][2] += xv0 * w.z; acc[0][3] += xv0 * w.w;
            acc[1][0] += xv1 * w.x; acc[1][1] += xv1 * w.y; acc[1][2] += xv1 * w.z; acc[1][3] += xv1 * w.w;
            acc[2][0] += xv2 * w.x; acc[2][1] += xv2 * w.y; acc[2][2] += xv2 * w.z; acc[2][3] += xv2 * w.w;
            acc[3][0] += xv3 * w.x; acc[3][1] += xv3 * w.y; acc[3][2] += xv3 * w.z; acc[3][3] += xv3 * w.w;
        }
        __syncthreads();
    }
#pragma unroll
    for (int j = 0; j < 4; j++) {
        float bb = b1[jq * 4 + j];
#pragma unroll
        for (int i = 0; i < 4; i++)
            xs[nq * 4 + i][jq * 4 + j] = fmaxf(acc[i][j] + bb, 0.0f);
    }
    __syncthreads();
#pragma unroll
    for (int r = 0; r < 4; r++) {
        int idx = tid * 4 + r;
        int n = idx >> 4, c = idx & 15;
        float s = b2[c];
#pragma unroll 8
        for (int k = 0; k < 64; k++) s += xs[n][k] * w2s[k][c];
        int gn = n0 + n;
        if (gn < Nn) {
            float gv = g_dis[gn] * s;
            g_h0[gn * CLS + c] = s;
            g_gA[gn * CLS + c] = gv;
            g_dh0[gn * CLS + c] = gv;
        }
    }
}

// ---------------- diffusion step (warp per node, float4 channels) ----------------
// intermediate: g' = 0.9*dis^2*S + 0.1*dh0     (S = sum over in-edges of g[src])
// final:        h  = 0.9*dis*S  + 0.1*h0
__global__ __launch_bounds__(256) void diffuse_kernel(int gsel, int d2, int is_final,
                                                      float* __restrict__ h_ext) {
    const float* __restrict__ gi = gsel ? g_gB : g_gA;
    float*       __restrict__ go = gsel ? g_gA : g_gB;

    int t = blockIdx.x * blockDim.x + threadIdx.x;
    int node = t >> 5;
    if (node >= Nn) return;
    int lane = t & 31;
    int eg = lane >> 2;   // edge slot 0..7
    int q  = lane & 3;    // channel group 0..3 (float4)

    int r0 = g_rowptr[node];
    int r1 = g_rowptr[node + 1];
    const float4* __restrict__ gi4 = reinterpret_cast<const float4*>(gi);

    float4 acc = make_float4(0.f, 0.f, 0.f, 0.f);
    for (int e = r0 + eg; e < r1; e += 8) {
        int col = g_col[e];
        float4 v = gi4[col * 4 + q];
        acc.x += v.x; acc.y += v.y; acc.z += v.z; acc.w += v.w;
    }
#pragma unroll
    for (int m = 16; m >= 4; m >>= 1) {
        acc.x += __shfl_xor_sync(0xffffffffu, acc.x, m);
        acc.y += __shfl_xor_sync(0xffffffffu, acc.y, m);
        acc.z += __shfl_xor_sync(0xffffffffu, acc.z, m);
        acc.w += __shfl_xor_sync(0xffffffffu, acc.w, m);
    }
    if (eg == 0) {
        if (!is_final) {
            float dd = g_dis2[node];
            float4 b = reinterpret_cast<const float4*>(g_dh0)[node * 4 + q];
            float4 o;
            o.x = 0.9f * dd * acc.x + 0.1f * b.x;
            o.y = 0.9f * dd * acc.y + 0.1f * b.y;
            o.z = 0.9f * dd * acc.z + 0.1f * b.z;
            o.w = 0.9f * dd * acc.w + 0.1f * b.w;
            reinterpret_cast<float4*>(go)[node * 4 + q] = o;
        } else {
            float dv = g_dis[node];
            const float* __restrict__ h0 = d2 ? g_out0 : g_h0;
            float* __restrict__ ho = h_ext ? h_ext : g_hA;
            float4 b = reinterpret_cast<const float4*>(h0)[node * 4 + q];
            float4 o;
            o.x = 0.9f * dv * acc.x + 0.1f * b.x;
            o.y = 0.9f * dv * acc.y + 0.1f * b.y;
            o.z = 0.9f * dv * acc.z + 0.1f * b.z;
            o.w = 0.9f * dv * acc.w + 0.1f * b.w;
            reinterpret_cast<float4*>(ho)[node * 4 + q] = o;
        }
    }
}

// ---------------- fused head: tf32 MMA GEMM + per-class epilogue ----------------
__global__ __launch_bounds__(256, 2) void head_kernel(
    const float* __restrict__ x, const float* __restrict__ A1w,
    const float* __restrict__ A1b, const float* __restrict__ A2w,
    const float* __restrict__ A2b) {
    __shared__ float As[64 * 36];
    __shared__ float Bs[32 * 264];
    __shared__ float a1w0s[4 * 64];
    __shared__ float a1bs[4 * 64];
    __shared__ float a2ws[4 * 64];
    __shared__ float outsum[64 * 4];

    int tid = threadIdx.x;
    int warp = tid >> 5, lane = tid & 31;
    int g = lane >> 2, q = lane & 3;
    int warp_m = warp >> 1;
    int warp_n = warp & 1;
    int n0 = blockIdx.x * 64;
    int c0 = blockIdx.y * 4;

    for (int i = tid; i < 256; i += 256) {
        int cl = i >> 6, h = i & 63;
        a1w0s[i] = A1w[(size_t)(c0 + cl) * A1W_STRIDE + h];
        a1bs[i]  = A1b[(c0 + cl) * HID + h];
        a2ws[i]  = A2w[(c0 + cl) * HID + h];
    }

    float acc[16][4];
#pragma unroll
    for (int i = 0; i < 16; i++)
#pragma unroll
        for (int j = 0; j < 4; j++) acc[i][j] = 0.0f;

    for (int kc = 0; kc < FEATS; kc += 32) {
        for (int i = tid; i < 64 * 32; i += 256) {
            int r = i >> 5, k = i & 31;
            int gn = n0 + r;
            float v = (gn < Nn) ? x[(size_t)gn * FEATS + kc + k] : 0.0f;
            As[r * 36 + k] = tf32r(v);
        }
        for (int i = tid; i < 32 * 256; i += 256) {
            int k = i >> 8, j = i & 255;
            int cl = j >> 6, h = j & 63;
            float v = A1w[(size_t)(c0 + cl) * A1W_STRIDE + (size_t)(1 + kc + k) * HID + h];
            Bs[k * 264 + j] = tf32r(v);
        }
        __syncthreads();
#pragma unroll
        for (int kk = 0; kk < 4; kk++) {
            int kb = kk * 8;
            int ar = warp_m * 16;
            uint32_t a0 = __float_as_uint(As[(ar + g) * 36 + kb + q]);
            uint32_t a1 = __float_as_uint(As[(ar + g + 8) * 36 + kb + q]);
            uint32_t a2 = __float_as_uint(As[(ar + g) * 36 + kb + q + 4]);
            uint32_t a3 = __float_as_uint(As[(ar + g + 8) * 36 + kb + q + 4]);
#pragma unroll
            for (int nt = 0; nt < 16; nt++) {
                int cb = warp_n * 128 + nt * 8;
                uint32_t b0 = __float_as_uint(Bs[(kb + q) * 264 + cb + g]);
                uint32_t b1 = __float_as_uint(Bs[(kb + q + 4) * 264 + cb + g]);
                asm volatile(
                    "mma.sync.aligned.m16n8k8.row.col.f32.tf32.tf32.f32 "
                    "{%0,%1,%2,%3}, {%4,%5,%6,%7}, {%8,%9}, {%0,%1,%2,%3};"
                    : "+f"(acc[nt][0]), "+f"(acc[nt][1]), "+f"(acc[nt][2]), "+f"(acc[nt][3])
                    : "r"(a0), "r"(a1), "r"(a2), "r"(a3), "r"(b0), "r"(b1));
            }
        }
        __syncthreads();
    }

    int nlA = warp_m * 16 + g;
    int nlB = nlA + 8;
    float hv[2][2];
#pragma unroll
    for (int rr = 0; rr < 2; rr++) {
#pragma unroll
        for (int ch = 0; ch < 2; ch++) {
            int node = n0 + (rr ? nlB : nlA);
            int cgl = c0 + warp_n * 2 + ch;
            hv[rr][ch] = (node < Nn) ? g_hA[node * CLS + cgl] : 0.0f;
        }
    }
    float p[2][2] = {{0.f, 0.f}, {0.f, 0.f}};
#pragma unroll
    for (int nt = 0; nt < 16; nt++) {
        int clh = nt >> 3;
        int cidx = warp_n * 2 + clh;
        int hbase = (nt & 7) * 8 + 2 * q;
#pragma unroll
        for (int cc = 0; cc < 2; cc++) {
            int h = hbase + cc;
            int sidx = cidx * 64 + h;
            float w0 = a1w0s[sidx], bb = a1bs[sidx], w2 = a2ws[sidx];
            float z0 = fmaxf(acc[nt][cc] + hv[0][clh] * w0 + bb, 0.0f);
            float z1 = fmaxf(acc[nt][2 + cc] + hv[1][clh] * w0 + bb, 0.0f);
            p[0][clh] += z0 * w2;
            p[1][clh] += z1 * w2;
        }
    }
#pragma unroll
    for (int rr = 0; rr < 2; rr++) {
#pragma unroll
        for (int ch = 0; ch < 2; ch++) {
            float v = p[rr][ch];
            v += __shfl_down_sync(0xffffffffu, v, 1, 4);
            v += __shfl_down_sync(0xffffffffu, v, 2, 4);
            if (q == 0) outsum[(warp_m * 16 + g + rr * 8) * 4 + (warp_n * 2 + ch)] = v;
        }
    }
    __syncthreads();
    {
        int nl = tid >> 2, cl = tid & 3;
        int node = n0 + nl;
        int cgl = c0 + cl;
        if (node < Nn) {
            float v = outsum[nl * 4 + cl] + A2b[cgl];
            float gv = g_dis[node] * v;
            g_out0[node * CLS + cgl] = v;
            g_gA[node * CLS + cgl] = gv;
            g_dh0[node * CLS + cgl] = gv;
        }
    }
}

// ---------------- launch ----------------
extern "C" void kernel_launch(void* const* d_in, const int* in_sizes, int n_in,
                              void* d_out, int out_size) {
    const float* x     = (const float*)d_in[0];
    const void*  edges = d_in[1];
    const float* W1    = (const float*)d_in[2];
    const float* b1    = (const float*)d_in[3];
    const float* W2    = (const float*)d_in[4];
    const float* b2    = (const float*)d_in[5];
    const float* A1w   = (const float*)d_in[6];
    const float* A1b   = (const float*)d_in[7];
    const float* A2w   = (const float*)d_in[8];
    const float* A2b   = (const float*)d_in[9];

    init_kernel<<<(Nn + 255) / 256, 256>>>((const int*)edges);
    deg_kernel<<<(Ee + 255) / 256, 256>>>(edges);
    scan_kernel<<<1, 1024>>>();
    fill_kernel<<<(Ee + 255) / 256, 256>>>(edges);

    mlp_kernel<<<(Nn + MLP_NB - 1) / MLP_NB, 256>>>(x, W1, b1, W2, b2);

    const int DIFF_GRID = (Nn * 32 + 255) / 256;
    for (int i = 0; i < DEPTH; i++)
        diffuse_kernel<<<DIFF_GRID, 256>>>(i & 1, 0, i == DEPTH - 1, nullptr);

    head_kernel<<<dim3((Nn + 63) / 64, 4), 256>>>(x, A1w, A1b, A2w, A2b);

    for (int i = 0; i < DEPTH; i++)
        diffuse_kernel<<<DIFF_GRID, 256>>>(i & 1, 1, i == DEPTH - 1,
            (i == DEPTH - 1) ? (float*)d_out : nullptr);
}

// round 7
// speedup vs baseline: 1.1450x; 1.1113x over previous
#include <cuda_runtime.h>
#include <cstdint>

#define Nn     100000
#define Ee     3200000
#define FEATS  256
#define CLS    16
#define HID    64
#define DEPTH  20
#define A1W_STRIDE (257*64)

#define FILL_BLOCKS 12500
#define MLP_BLOCKS  1563

// ---------------- scratch (static device globals; no allocation) ----------------
__device__ int   g_is64;
__device__ int   g_deg[Nn];          // must be zero at entry; cleanup kernel re-zeroes at end
__device__ int   g_rowptr[Nn + 1];
__device__ int   g_cursor[Nn];
__device__ int   g_col[Ee];          // src indices sorted by dst (CSR by dst)
__device__ float g_dis[Nn];
__device__ float g_dis2[Nn];
__device__ float g_h0[Nn * CLS];     // MLP output (diffusion-1 anchor)
__device__ float g_hA[Nn * CLS];     // diffusion-1 h output
__device__ float g_out0[Nn * CLS];   // head output (diffusion-2 anchor)
__device__ float g_dh0[Nn * CLS];    // dis * h0 (anchor premultiplied)
__device__ float g_gA[Nn * CLS];     // ping-pong g = dis*h
__device__ float g_gB[Nn * CLS];

// ---------------- helpers ----------------
__device__ __forceinline__ float tf32r(float x) {
    uint32_t y;
    asm("cvt.rna.tf32.f32 %0, %1;" : "=r"(y) : "f"(x));
    return __uint_as_float(y);
}

// ---------------- degree count (+ int64/int32 edge dtype detection) ----------------
__global__ __launch_bounds__(256) void deg_kernel(const void* __restrict__ edges) {
    __shared__ int s_is64;
    const int* e32 = (const int*)edges;
    if (threadIdx.x < 32) {
        int nz = 0;
        for (int i = threadIdx.x; i < 2048; i += 32) nz += (e32[2 * i + 1] != 0);
        for (int o = 16; o; o >>= 1) nz += __shfl_down_sync(0xffffffffu, nz, o);
        if (threadIdx.x == 0) {
            s_is64 = (nz == 0) ? 1 : 0;
            if (blockIdx.x == 0) g_is64 = s_is64;
        }
    }
    __syncthreads();
    int is64 = s_is64;
    int e = blockIdx.x * blockDim.x + threadIdx.x;
    if (e < Ee) {
        int d = is64 ? (int)((const long long*)edges)[(long long)Ee + e] : e32[Ee + e];
        atomicAdd(&g_deg[d], 1);
    }
}

// ---------------- fused coalesced scan: rowptr/cursor/dis/dis2 ----------------
// 98 blocks x 256 threads; block b owns nodes [b*1024, b*1024+1024).
// Redundant-prefix: each block coalesced-sums deg[0..base) (L2-hot, ~400KB total).
__global__ __launch_bounds__(256) void scan_kernel() {
    __shared__ int s_red[8];
    __shared__ int s_scan[9];
    int b = blockIdx.x, tid = threadIdx.x;
    int base = b << 10;
    int n_here = min(1024, Nn - base);

    // prefix over all preceding degrees (coalesced)
    int ps = 0;
    for (int i = tid; i < base; i += 256) ps += g_deg[i];
    for (int o = 16; o; o >>= 1) ps += __shfl_down_sync(0xffffffffu, ps, o);
    if ((tid & 31) == 0) s_red[tid >> 5] = ps;
    __syncthreads();
    if (tid == 0) {
        int t = 0;
        for (int w = 0; w < 8; w++) t += s_red[w];
        s_scan[8] = t;
    }
    __syncthreads();
    int offset = s_scan[8];

    // local exclusive scan of 1024 degrees (4 per thread)
    int i0 = tid * 4;
    int d0 = 0, d1 = 0, d2 = 0, d3 = 0;
    bool act = (i0 < n_here);
    if (act) {
        d0 = g_deg[base + i0];
        d1 = g_deg[base + i0 + 1];
        d2 = g_deg[base + i0 + 2];
        d3 = g_deg[base + i0 + 3];
    }
    int ts = d0 + d1 + d2 + d3;
    int incl = ts;
    for (int o = 1; o < 32; o <<= 1) {
        int v = __shfl_up_sync(0xffffffffu, incl, o);
        if ((tid & 31) >= o) incl += v;
    }
    if ((tid & 31) == 31) s_scan[tid >> 5] = incl;
    __syncthreads();
    if (tid == 0) {
        int r = 0;
        for (int w = 0; w < 8; w++) { int t = s_scan[w]; s_scan[w] = r; r += t; }
    }
    __syncthreads();
    int texcl = s_scan[tid >> 5] + incl - ts;
    if (act) {
        int run = offset + texcl;
        int n = base + i0;
        int dd[4] = {d0, d1, d2, d3};
#pragma unroll
        for (int j = 0; j < 4; j++) {
            g_rowptr[n + j] = run;
            g_cursor[n + j] = run;
            float dv = (dd[j] > 0) ? rsqrtf((float)dd[j]) : 0.0f;
            g_dis[n + j] = dv;
            g_dis2[n + j] = dv * dv;
            run += dd[j];
        }
        if (n + 4 == Nn) g_rowptr[Nn] = run;
    }
}

// ---------------- merged fill (CSR scatter) + MLP kernel ----------------
// grid = 9*MLP_BLOCKS; blockIdx%9==8 -> mlp role (1563 blocks), else fill role (12500).
#define MLP_NB 64
__global__ __launch_bounds__(256) void fillmlp_kernel(
    const void* __restrict__ edges,
    const float* __restrict__ x, const float* __restrict__ W1,
    const float* __restrict__ b1, const float* __restrict__ W2,
    const float* __restrict__ b2) {
    __shared__ float xs[MLP_NB][65];
    __shared__ float w1s[64][64];
    __shared__ float w2s[64][16];

    int m = blockIdx.x / 9, r = blockIdx.x % 9;
    int tid = threadIdx.x;

    if (r < 8) {
        // ---- fill role ----
        int fb = m * 8 + r;
        if (fb >= FILL_BLOCKS) return;
        int e = fb * 256 + tid;
        if (e < Ee) {
            int is64 = g_is64;
            int s, d;
            if (is64) {
                s = (int)((const long long*)edges)[e];
                d = (int)((const long long*)edges)[(long long)Ee + e];
            } else {
                s = ((const int*)edges)[e];
                d = ((const int*)edges)[Ee + e];
            }
            int p = atomicAdd(&g_cursor[d], 1);
            g_col[p] = s;
        }
        return;
    }

    // ---- mlp role: h0 = relu(x@W1+b1)@W2 + b2 ; gA = dh0 = dis*h0 ----
    if (m >= MLP_BLOCKS) return;
    int n0 = m * MLP_NB;
    int nq = tid >> 4;
    int jq = tid & 15;

    for (int i = tid; i < 64 * 16; i += 256) w2s[i >> 4][i & 15] = W2[i];

    float acc[4][4];
#pragma unroll
    for (int i = 0; i < 4; i++)
#pragma unroll
        for (int j = 0; j < 4; j++) acc[i][j] = 0.0f;

    for (int kc = 0; kc < FEATS; kc += 64) {
        for (int i = tid; i < 64 * 64; i += 256) {
            int n = i >> 6, k = i & 63;
            int gn = n0 + n;
            xs[n][k] = (gn < Nn) ? x[(size_t)gn * FEATS + kc + k] : 0.0f;
        }
        for (int i = tid; i < 64 * 64; i += 256) {
            int k = i >> 6, j = i & 63;
            w1s[k][j] = W1[(size_t)(kc + k) * HID + j];
        }
        __syncthreads();
#pragma unroll 8
        for (int k = 0; k < 64; k++) {
            float xv0 = xs[nq * 4 + 0][k];
            float xv1 = xs[nq * 4 + 1][k];
            float xv2 = xs[nq * 4 + 2][k];
            float xv3 = xs[nq * 4 + 3][k];
            float4 w = *reinterpret_cast<const float4*>(&w1s[k][jq * 4]);
            acc[0][0] += xv0 * w.x; acc[0][1] += xv0 * w.y; acc[0][2] += xv0 * w.z; acc[0][3] += xv0 * w.w;
            acc[1][0] += xv1 * w.x; acc[1][1] += xv1 * w.y; acc[1][2] += xv1 * w.z; acc[1][3] += xv1 * w.w;
            acc[2][0] += xv2 * w.x; acc[2][1] += xv2 * w.y; acc[2][2] += xv2 * w.z; acc[2][3] += xv2 * w.w;
            acc[3][0] += xv3 * w.x; acc[3][1] += xv3 * w.y; acc[3][2] += xv3 * w.z; acc[3][3] += xv3 * w.w;
        }
        __syncthreads();
    }
#pragma unroll
    for (int j = 0; j < 4; j++) {
        float bb = b1[jq * 4 + j];
#pragma unroll
        for (int i = 0; i < 4; i++)
            xs[nq * 4 + i][jq * 4 + j] = fmaxf(acc[i][j] + bb, 0.0f);
    }
    __syncthreads();
#pragma unroll
    for (int rr = 0; rr < 4; rr++) {
        int idx = tid * 4 + rr;
        int n = idx >> 4, c = idx & 15;
        float s = b2[c];
#pragma unroll 8
        for (int k = 0; k < 64; k++) s += xs[n][k] * w2s[k][c];
        int gn = n0 + n;
        if (gn < Nn) {
            float gv = g_dis[gn] * s;
            g_h0[gn * CLS + c] = s;
            g_gA[gn * CLS + c] = gv;
            g_dh0[gn * CLS + c] = gv;
        }
    }
}

// ---------------- diffusion step (warp/node, float4 channels, 2-deep pipeline) ----
// intermediate: g' = 0.9*dis^2*S + 0.1*dh0     (S = sum over in-edges of g[src])
// final:        h  = 0.9*dis*S  + 0.1*h0
__global__ __launch_bounds__(256) void diffuse_kernel(int gsel, int d2, int is_final,
                                                      float* __restrict__ h_ext) {
    const float* __restrict__ gi = gsel ? g_gB : g_gA;
    float*       __restrict__ go = gsel ? g_gA : g_gB;

    int t = blockIdx.x * blockDim.x + threadIdx.x;
    int node = t >> 5;
    if (node >= Nn) return;
    int lane = t & 31;
    int eg = lane >> 2;   // edge slot 0..7
    int q  = lane & 3;    // channel group 0..3 (float4)

    int r0 = g_rowptr[node];
    int r1 = g_rowptr[node + 1];
    const float4* __restrict__ gi4 = reinterpret_cast<const float4*>(gi);

    float4 a0 = make_float4(0.f, 0.f, 0.f, 0.f);
    float4 a1 = make_float4(0.f, 0.f, 0.f, 0.f);
    int e = r0 + eg;
    for (; e + 8 < r1; e += 16) {
        int cA = __ldg(&g_col[e]);
        int cB = __ldg(&g_col[e + 8]);
        float4 vA = gi4[cA * 4 + q];
        float4 vB = gi4[cB * 4 + q];
        a0.x += vA.x; a0.y += vA.y; a0.z += vA.z; a0.w += vA.w;
        a1.x += vB.x; a1.y += vB.y; a1.z += vB.z; a1.w += vB.w;
    }
    if (e < r1) {
        int c = __ldg(&g_col[e]);
        float4 v = gi4[c * 4 + q];
        a0.x += v.x; a0.y += v.y; a0.z += v.z; a0.w += v.w;
    }
    float4 acc;
    acc.x = a0.x + a1.x; acc.y = a0.y + a1.y;
    acc.z = a0.z + a1.z; acc.w = a0.w + a1.w;
#pragma unroll
    for (int mm = 16; mm >= 4; mm >>= 1) {
        acc.x += __shfl_xor_sync(0xffffffffu, acc.x, mm);
        acc.y += __shfl_xor_sync(0xffffffffu, acc.y, mm);
        acc.z += __shfl_xor_sync(0xffffffffu, acc.z, mm);
        acc.w += __shfl_xor_sync(0xffffffffu, acc.w, mm);
    }
    if (eg == 0) {
        if (!is_final) {
            float dd = g_dis2[node];
            float4 b = reinterpret_cast<const float4*>(g_dh0)[node * 4 + q];
            float4 o;
            o.x = 0.9f * dd * acc.x + 0.1f * b.x;
            o.y = 0.9f * dd * acc.y + 0.1f * b.y;
            o.z = 0.9f * dd * acc.z + 0.1f * b.z;
            o.w = 0.9f * dd * acc.w + 0.1f * b.w;
            reinterpret_cast<float4*>(go)[node * 4 + q] = o;
        } else {
            float dv = g_dis[node];
            const float* __restrict__ h0 = d2 ? g_out0 : g_h0;
            float* __restrict__ ho = h_ext ? h_ext : g_hA;
            float4 b = reinterpret_cast<const float4*>(h0)[node * 4 + q];
            float4 o;
            o.x = 0.9f * dv * acc.x + 0.1f * b.x;
            o.y = 0.9f * dv * acc.y + 0.1f * b.y;
            o.z = 0.9f * dv * acc.z + 0.1f * b.z;
            o.w = 0.9f * dv * acc.w + 0.1f * b.w;
            reinterpret_cast<float4*>(ho)[node * 4 + q] = o;
        }
    }
}

// ---------------- fused head: tf32 MMA GEMM + per-class epilogue ----------------
__global__ __launch_bounds__(256, 2) void head_kernel(
    const float* __restrict__ x, const float* __restrict__ A1w,
    const float* __restrict__ A1b, const float* __restrict__ A2w,
    const float* __restrict__ A2b) {
    __shared__ float As[64 * 36];
    __shared__ float Bs[32 * 264];
    __shared__ float a1w0s[4 * 64];
    __shared__ float a1bs[4 * 64];
    __shared__ float a2ws[4 * 64];
    __shared__ float outsum[64 * 4];

    int tid = threadIdx.x;
    int warp = tid >> 5, lane = tid & 31;
    int g = lane >> 2, q = lane & 3;
    int warp_m = warp >> 1;
    int warp_n = warp & 1;
    int n0 = blockIdx.x * 64;
    int c0 = blockIdx.y * 4;

    for (int i = tid; i < 256; i += 256) {
        int cl = i >> 6, h = i & 63;
        a1w0s[i] = A1w[(size_t)(c0 + cl) * A1W_STRIDE + h];
        a1bs[i]  = A1b[(c0 + cl) * HID + h];
        a2ws[i]  = A2w[(c0 + cl) * HID + h];
    }

    float acc[16][4];
#pragma unroll
    for (int i = 0; i < 16; i++)
#pragma unroll
        for (int j = 0; j < 4; j++) acc[i][j] = 0.0f;

    for (int kc = 0; kc < FEATS; kc += 32) {
        for (int i = tid; i < 64 * 32; i += 256) {
            int rr = i >> 5, k = i & 31;
            int gn = n0 + rr;
            float v = (gn < Nn) ? x[(size_t)gn * FEATS + kc + k] : 0.0f;
            As[rr * 36 + k] = tf32r(v);
        }
        for (int i = tid; i < 32 * 256; i += 256) {
            int k = i >> 8, j = i & 255;
            int cl = j >> 6, h = j & 63;
            float v = A1w[(size_t)(c0 + cl) * A1W_STRIDE + (size_t)(1 + kc + k) * HID + h];
            Bs[k * 264 + j] = tf32r(v);
        }
        __syncthreads();
#pragma unroll
        for (int kk = 0; kk < 4; kk++) {
            int kb = kk * 8;
            int ar = warp_m * 16;
            uint32_t a0 = __float_as_uint(As[(ar + g) * 36 + kb + q]);
            uint32_t a1 = __float_as_uint(As[(ar + g + 8) * 36 + kb + q]);
            uint32_t a2 = __float_as_uint(As[(ar + g) * 36 + kb + q + 4]);
            uint32_t a3 = __float_as_uint(As[(ar + g + 8) * 36 + kb + q + 4]);
#pragma unroll
            for (int nt = 0; nt < 16; nt++) {
                int cb = warp_n * 128 + nt * 8;
                uint32_t b0 = __float_as_uint(Bs[(kb + q) * 264 + cb + g]);
                uint32_t b1 = __float_as_uint(Bs[(kb + q + 4) * 264 + cb + g]);
                asm volatile(
                    "mma.sync.aligned.m16n8k8.row.col.f32.tf32.tf32.f32 "
                    "{%0,%1,%2,%3}, {%4,%5,%6,%7}, {%8,%9}, {%0,%1,%2,%3};"
                    : "+f"(acc[nt][0]), "+f"(acc[nt][1]), "+f"(acc[nt][2]), "+f"(acc[nt][3])
                    : "r"(a0), "r"(a1), "r"(a2), "r"(a3), "r"(b0), "r"(b1));
            }
        }
        __syncthreads();
    }

    int nlA = warp_m * 16 + g;
    int nlB = nlA + 8;
    float hv[2][2];
#pragma unroll
    for (int rr = 0; rr < 2; rr++) {
#pragma unroll
        for (int ch = 0; ch < 2; ch++) {
            int node = n0 + (rr ? nlB : nlA);
            int cgl = c0 + warp_n * 2 + ch;
            hv[rr][ch] = (node < Nn) ? g_hA[node * CLS + cgl] : 0.0f;
        }
    }
    float p[2][2] = {{0.f, 0.f}, {0.f, 0.f}};
#pragma unroll
    for (int nt = 0; nt < 16; nt++) {
        int clh = nt >> 3;
        int cidx = warp_n * 2 + clh;
        int hbase = (nt & 7) * 8 + 2 * q;
#pragma unroll
        for (int cc = 0; cc < 2; cc++) {
            int h = hbase + cc;
            int sidx = cidx * 64 + h;
            float w0 = a1w0s[sidx], bb = a1bs[sidx], w2 = a2ws[sidx];
            float z0 = fmaxf(acc[nt][cc] + hv[0][clh] * w0 + bb, 0.0f);
            float z1 = fmaxf(acc[nt][2 + cc] + hv[1][clh] * w0 + bb, 0.0f);
            p[0][clh] += z0 * w2;
            p[1][clh] += z1 * w2;
        }
    }
#pragma unroll
    for (int rr = 0; rr < 2; rr++) {
#pragma unroll
        for (int ch = 0; ch < 2; ch++) {
            float v = p[rr][ch];
            v += __shfl_down_sync(0xffffffffu, v, 1, 4);
            v += __shfl_down_sync(0xffffffffu, v, 2, 4);
            if (q == 0) outsum[(warp_m * 16 + g + rr * 8) * 4 + (warp_n * 2 + ch)] = v;
        }
    }
    __syncthreads();
    {
        int nl = tid >> 2, cl = tid & 3;
        int node = n0 + nl;
        int cgl = c0 + cl;
        if (node < Nn) {
            float v = outsum[nl * 4 + cl] + A2b[cgl];
            float gv = g_dis[node] * v;
            g_out0[node * CLS + cgl] = v;
            g_gA[node * CLS + cgl] = gv;
            g_dh0[node * CLS + cgl] = gv;
        }
    }
}

// zero g_deg for the NEXT invocation (globals are zero at module load)
__global__ void cleanup_kernel() {
    int n = blockIdx.x * blockDim.x + threadIdx.x;
    if (n < Nn) g_deg[n] = 0;
}

// ---------------- launch ----------------
extern "C" void kernel_launch(void* const* d_in, const int* in_sizes, int n_in,
                              void* d_out, int out_size) {
    const float* x     = (const float*)d_in[0];
    const void*  edges = d_in[1];
    const float* W1    = (const float*)d_in[2];
    const float* b1    = (const float*)d_in[3];
    const float* W2    = (const float*)d_in[4];
    const float* b2    = (const float*)d_in[5];
    const float* A1w   = (const float*)d_in[6];
    const float* A1b   = (const float*)d_in[7];
    const float* A2w   = (const float*)d_in[8];
    const float* A2b   = (const float*)d_in[9];

    deg_kernel<<<FILL_BLOCKS, 256>>>(edges);
    scan_kernel<<<(Nn + 1023) / 1024, 256>>>();
    fillmlp_kernel<<<9 * MLP_BLOCKS, 256>>>(edges, x, W1, b1, W2, b2);

    const int DIFF_GRID = (Nn * 32 + 255) / 256;
    for (int i = 0; i < DEPTH; i++)
        diffuse_kernel<<<DIFF_GRID, 256>>>(i & 1, 0, i == DEPTH - 1, nullptr);

    head_kernel<<<dim3((Nn + 63) / 64, 4), 256>>>(x, A1w, A1b, A2w, A2b);

    for (int i = 0; i < DEPTH; i++)
        diffuse_kernel<<<DIFF_GRID, 256>>>(i & 1, 1, i == DEPTH - 1,
            (i == DEPTH - 1) ? (float*)d_out : nullptr);

    cleanup_kernel<<<(Nn + 255) / 256, 256>>>();
}